// round 1
// baseline (speedup 1.0000x reference)
#include <cuda_runtime.h>
#include <cstdint>
#include <cstddef>

// Problem constants
#define BATCH 8
#define SEQK  8192
#define CDIM  512
#define TDIM  256
#define HEADS 8
#define DH    64

// ---------------- scratch (device globals; no allocation allowed) -----------
__device__ float g_q[TDIM * CDIM];                                  // scaled q
__device__ float g_kv[(size_t)BATCH * SEQK * 2 * CDIM];             // k|v, 268MB
__device__ float g_ctx[(size_t)BATCH * TDIM * CDIM];                // attn out
__device__ float g_y[(size_t)BATCH * TDIM * CDIM];                  // pre-LN

// ---------------- packed fp32x2 helpers (FFMA2 path, sm_100+) ---------------
__device__ __forceinline__ unsigned long long pk2(float a, float b) {
    unsigned long long r;
    asm("mov.b64 %0, {%1, %2};" : "=l"(r) : "f"(a), "f"(b));
    return r;
}
__device__ __forceinline__ void fma2(unsigned long long& d,
                                     unsigned long long a, unsigned long long b) {
    asm("fma.rn.f32x2 %0, %1, %2, %0;" : "+l"(d) : "l"(a), "l"(b));
}
__device__ __forceinline__ void mul2(unsigned long long& d, unsigned long long a) {
    asm("mul.rn.f32x2 %0, %0, %1;" : "+l"(d) : "l"(a));
}
__device__ __forceinline__ float2 up2(unsigned long long v) {
    float lo, hi;
    asm("mov.b64 {%0, %1}, %2;" : "=f"(lo), "=f"(hi) : "l"(v));
    return make_float2(lo, hi);
}

// ---------------- generic tiled GEMM: Out = (A @ W[nOff:]^T + bias)*alpha + resid
// A: [M,Kd] row-major.  W: rows are output channels, row length Kd.
// BM=BN=128, BK=8, 256 threads, 8x8 per thread via f32x2.
__global__ void __launch_bounds__(256, 2)
gemm_kernel(const float* __restrict__ A,
            const float* __restrict__ W, int nOff,
            const float* __restrict__ bias,
            float alpha,
            const float* __restrict__ resid,   // row = m % TDIM, len N (or null)
            float* __restrict__ Out,
            int M, int N, int Kd)
{
    __shared__ float sA[2][8][128];
    __shared__ float sB[2][8][128];

    const int tid = threadIdx.x;
    const int tm  = tid >> 4;          // 0..15
    const int tn  = tid & 15;          // 0..15
    const int m0  = blockIdx.y * 128;
    const int n0  = blockIdx.x * 128;
    const int lr  = tid >> 1;          // 0..127
    const int lq  = tid & 1;           // 0..1

    const float* Aload = A + (size_t)(m0 + lr) * Kd + lq * 4;
    const float* Wload = W + (size_t)(n0 + lr + nOff) * Kd + lq * 4;

    unsigned long long acc[8][4];
#pragma unroll
    for (int i = 0; i < 8; i++)
#pragma unroll
        for (int j = 0; j < 4; j++) acc[i][j] = 0ull;

    // prologue: panel 0
    {
        float4 av = *(const float4*)(Aload);
        sA[0][lq*4+0][lr] = av.x; sA[0][lq*4+1][lr] = av.y;
        sA[0][lq*4+2][lr] = av.z; sA[0][lq*4+3][lr] = av.w;
        float4 bv = *(const float4*)(Wload);
        sB[0][lq*4+0][lr] = bv.x; sB[0][lq*4+1][lr] = bv.y;
        sB[0][lq*4+2][lr] = bv.z; sB[0][lq*4+3][lr] = bv.w;
    }
    __syncthreads();

    const int nPan = Kd >> 3;
    for (int p = 0; p < nPan; p++) {
        const int buf = p & 1;
        if (p + 1 < nPan) {
            const int nb = buf ^ 1;
            float4 av = *(const float4*)(Aload + (p + 1) * 8);
            float4 bv = *(const float4*)(Wload + (p + 1) * 8);
            sA[nb][lq*4+0][lr] = av.x; sA[nb][lq*4+1][lr] = av.y;
            sA[nb][lq*4+2][lr] = av.z; sA[nb][lq*4+3][lr] = av.w;
            sB[nb][lq*4+0][lr] = bv.x; sB[nb][lq*4+1][lr] = bv.y;
            sB[nb][lq*4+2][lr] = bv.z; sB[nb][lq*4+3][lr] = bv.w;
        }
#pragma unroll
        for (int kk = 0; kk < 8; kk++) {
            float4 a0 = *(const float4*)&sA[buf][kk][tm*8];
            float4 a1 = *(const float4*)&sA[buf][kk][tm*8+4];
            float4 b0 = *(const float4*)&sB[buf][kk][tn*8];
            float4 b1 = *(const float4*)&sB[buf][kk][tn*8+4];
            unsigned long long bp0 = pk2(b0.x, b0.y);
            unsigned long long bp1 = pk2(b0.z, b0.w);
            unsigned long long bp2 = pk2(b1.x, b1.y);
            unsigned long long bp3 = pk2(b1.z, b1.w);
            float ra[8] = {a0.x,a0.y,a0.z,a0.w,a1.x,a1.y,a1.z,a1.w};
#pragma unroll
            for (int i = 0; i < 8; i++) {
                unsigned long long ap = pk2(ra[i], ra[i]);
                fma2(acc[i][0], ap, bp0);
                fma2(acc[i][1], ap, bp1);
                fma2(acc[i][2], ap, bp2);
                fma2(acc[i][3], ap, bp3);
            }
        }
        __syncthreads();
    }

    // epilogue
#pragma unroll
    for (int i = 0; i < 8; i++) {
        const int m = m0 + tm * 8 + i;
        const float* rrow = resid ? (resid + (size_t)(m & (TDIM - 1)) * N) : nullptr;
#pragma unroll
        for (int jp = 0; jp < 2; jp++) {
            const int n = n0 + tn * 8 + jp * 4;
            float2 v0 = up2(acc[i][jp*2+0]);
            float2 v1 = up2(acc[i][jp*2+1]);
            float4 o;
            o.x = (v0.x + bias[n+0]) * alpha;
            o.y = (v0.y + bias[n+1]) * alpha;
            o.z = (v1.x + bias[n+2]) * alpha;
            o.w = (v1.y + bias[n+3]) * alpha;
            if (rrow) { o.x += rrow[n+0]; o.y += rrow[n+1]; o.z += rrow[n+2]; o.w += rrow[n+3]; }
            *(float4*)(Out + (size_t)m * N + n) = o;
        }
    }
}

// ---------------- fused attention: per (b, h, 64-query tile), online softmax
// smem: Q^T (16K) + {K^T | P^T} union (16K, XOR-swizzled for P) + V (16K) = 48KB
__global__ void __launch_bounds__(256, 2)
attn_kernel(const float* __restrict__ q,    // [TDIM, CDIM], pre-scaled by 1/8
            const float* __restrict__ kv,   // [B*SEQK, 2*CDIM]
            float* __restrict__ ctx)        // [B*TDIM, CDIM]
{
    __shared__ float sQt[64 * 64];   // [d][t]
    __shared__ float sKS[64 * 64];   // phase 1: K^T [d][k]; phase 2: P^T [k][t^sw]
    __shared__ float sV [64 * 64];   // [k][d]

    const int tid = threadIdx.x;
    const int ty = tid >> 4, tx = tid & 15;
    const int t0 = blockIdx.x * 64;
    const int h  = blockIdx.y;
    const int b  = blockIdx.z;

    // load Q tile transposed (once)
    {
        const int tok = tid >> 2, fq = tid & 3;
        const float* qrow = q + (size_t)(t0 + tok) * CDIM + h * DH;
#pragma unroll
        for (int i = 0; i < 4; i++) {
            const int d4 = fq + i * 4;
            float4 v = *(const float4*)(qrow + d4 * 4);
            sQt[(d4*4+0)*64 + tok] = v.x;
            sQt[(d4*4+1)*64 + tok] = v.y;
            sQt[(d4*4+2)*64 + tok] = v.z;
            sQt[(d4*4+3)*64 + tok] = v.w;
        }
    }

    float mst[4], lst[4];
    unsigned long long acc[4][2];
#pragma unroll
    for (int i = 0; i < 4; i++) {
        mst[i] = -1e30f; lst[i] = 0.0f;
        acc[i][0] = 0ull; acc[i][1] = 0ull;
    }

    const float* kvbase = kv + (size_t)b * SEQK * (2 * CDIM) + h * DH;

    for (int kc = 0; kc < SEQK / 64; kc++) {
        // load K chunk transposed + V chunk natural
        {
            const int tok = tid >> 2, fq = tid & 3;
            const float* krow = kvbase + (size_t)(kc * 64 + tok) * (2 * CDIM);
#pragma unroll
            for (int i = 0; i < 4; i++) {
                const int d4 = fq + i * 4;
                float4 kvv = *(const float4*)(krow + d4 * 4);
                sKS[(d4*4+0)*64 + tok] = kvv.x;
                sKS[(d4*4+1)*64 + tok] = kvv.y;
                sKS[(d4*4+2)*64 + tok] = kvv.z;
                sKS[(d4*4+3)*64 + tok] = kvv.w;
                float4 vvv = *(const float4*)(krow + CDIM + d4 * 4);
                *(float4*)(sV + tok * 64 + d4 * 4) = vvv;
            }
        }
        __syncthreads();

        // S = Q K^T  (4 t-rows x 4 k-cols per thread, packed over k pairs)
        unsigned long long s2[4][2];
#pragma unroll
        for (int i = 0; i < 4; i++) { s2[i][0] = 0ull; s2[i][1] = 0ull; }
#pragma unroll 8
        for (int d = 0; d < 64; d++) {
            float4 qv  = *(const float4*)&sQt[d * 64 + ty * 4];
            float4 kk4 = *(const float4*)&sKS[d * 64 + tx * 4];
            unsigned long long k01 = pk2(kk4.x, kk4.y);
            unsigned long long k23 = pk2(kk4.z, kk4.w);
            unsigned long long q0 = pk2(qv.x, qv.x);
            unsigned long long q1 = pk2(qv.y, qv.y);
            unsigned long long q2 = pk2(qv.z, qv.z);
            unsigned long long q3 = pk2(qv.w, qv.w);
            fma2(s2[0][0], q0, k01); fma2(s2[0][1], q0, k23);
            fma2(s2[1][0], q1, k01); fma2(s2[1][1], q1, k23);
            fma2(s2[2][0], q2, k01); fma2(s2[2][1], q2, k23);
            fma2(s2[3][0], q3, k01); fma2(s2[3][1], q3, k23);
        }

        // online softmax update (row group = 16 lanes sharing ty)
        float p[4][4];
#pragma unroll
        for (int i = 0; i < 4; i++) {
            float2 sa = up2(s2[i][0]);
            float2 sb = up2(s2[i][1]);
            float rmax = fmaxf(fmaxf(sa.x, sa.y), fmaxf(sb.x, sb.y));
            rmax = fmaxf(rmax, __shfl_xor_sync(0xffffffffu, rmax, 1));
            rmax = fmaxf(rmax, __shfl_xor_sync(0xffffffffu, rmax, 2));
            rmax = fmaxf(rmax, __shfl_xor_sync(0xffffffffu, rmax, 4));
            rmax = fmaxf(rmax, __shfl_xor_sync(0xffffffffu, rmax, 8));
            float mnew = fmaxf(mst[i], rmax);
            float al = __expf(mst[i] - mnew);
            p[i][0] = __expf(sa.x - mnew);
            p[i][1] = __expf(sa.y - mnew);
            p[i][2] = __expf(sb.x - mnew);
            p[i][3] = __expf(sb.y - mnew);
            float rs = (p[i][0] + p[i][1]) + (p[i][2] + p[i][3]);
            rs += __shfl_xor_sync(0xffffffffu, rs, 1);
            rs += __shfl_xor_sync(0xffffffffu, rs, 2);
            rs += __shfl_xor_sync(0xffffffffu, rs, 4);
            rs += __shfl_xor_sync(0xffffffffu, rs, 8);
            lst[i] = lst[i] * al + rs;
            mst[i] = mnew;
            unsigned long long al2 = pk2(al, al);
            mul2(acc[i][0], al2);
            mul2(acc[i][1], al2);
        }
        __syncthreads();   // everyone done reading K^T before P^T overwrites it

        // write P^T (swizzled to dodge stride-64 column bank conflicts)
#pragma unroll
        for (int j = 0; j < 4; j++) {
            const int kr = tx * 4 + j;
            const int sw = kr & 31;
#pragma unroll
            for (int i = 0; i < 4; i++)
                sKS[kr * 64 + ((ty * 4 + i) ^ sw)] = p[i][j];
        }
        __syncthreads();

        // acc += P V  (contraction over chunk keys)
#pragma unroll 8
        for (int kkx = 0; kkx < 64; kkx++) {
            float4 vv = *(const float4*)&sV[kkx * 64 + tx * 4];
            unsigned long long v01 = pk2(vv.x, vv.y);
            unsigned long long v23 = pk2(vv.z, vv.w);
            const int sw = kkx & 31;
            const int base = kkx * 64;
            float p0 = sKS[base + ((ty*4+0) ^ sw)];
            float p1 = sKS[base + ((ty*4+1) ^ sw)];
            float p2 = sKS[base + ((ty*4+2) ^ sw)];
            float p3 = sKS[base + ((ty*4+3) ^ sw)];
            fma2(acc[0][0], pk2(p0,p0), v01); fma2(acc[0][1], pk2(p0,p0), v23);
            fma2(acc[1][0], pk2(p1,p1), v01); fma2(acc[1][1], pk2(p1,p1), v23);
            fma2(acc[2][0], pk2(p2,p2), v01); fma2(acc[2][1], pk2(p2,p2), v23);
            fma2(acc[3][0], pk2(p3,p3), v01); fma2(acc[3][1], pk2(p3,p3), v23);
        }
        __syncthreads();   // before next chunk overwrites sKS/sV
    }

    // epilogue: ctx = acc / l
#pragma unroll
    for (int i = 0; i < 4; i++) {
        const float inv = 1.0f / lst[i];
        float2 a0 = up2(acc[i][0]);
        float2 a1 = up2(acc[i][1]);
        float4 o = make_float4(a0.x * inv, a0.y * inv, a1.x * inv, a1.y * inv);
        const int t = t0 + ty * 4 + i;
        *(float4*)(ctx + (size_t)(b * TDIM + t) * CDIM + h * DH + tx * 4) = o;
    }
}

// ---------------- LayerNorm over C=512 -------------------------------------
__global__ void __launch_bounds__(256)
ln_kernel(const float* __restrict__ y, const float* __restrict__ gamma,
          const float* __restrict__ beta, float* __restrict__ out)
{
    __shared__ float2 sred[8];
    const int row = blockIdx.x;
    const int tid = threadIdx.x;
    const float* yr = y + (size_t)row * CDIM;
    float2 v = *(const float2*)(yr + tid * 2);
    float s1 = v.x + v.y;
    float s2 = v.x * v.x + v.y * v.y;
#pragma unroll
    for (int o = 16; o > 0; o >>= 1) {
        s1 += __shfl_xor_sync(0xffffffffu, s1, o);
        s2 += __shfl_xor_sync(0xffffffffu, s2, o);
    }
    if ((tid & 31) == 0) sred[tid >> 5] = make_float2(s1, s2);
    __syncthreads();
    float t1 = 0.f, t2 = 0.f;
#pragma unroll
    for (int i = 0; i < 8; i++) { t1 += sred[i].x; t2 += sred[i].y; }
    const float mean = t1 * (1.0f / CDIM);
    const float var  = t2 * (1.0f / CDIM) - mean * mean;
    const float rstd = rsqrtf(var + 1e-5f);
    const int c = tid * 2;
    float2 g = *(const float2*)(gamma + c);
    float2 be = *(const float2*)(beta + c);
    float2 o;
    o.x = (v.x - mean) * rstd * g.x + be.x;
    o.y = (v.y - mean) * rstd * g.y + be.y;
    *(float2*)(out + (size_t)row * CDIM + c) = o;
}

// ---------------- launch ----------------------------------------------------
extern "C" void kernel_launch(void* const* d_in, const int* in_sizes, int n_in,
                              void* d_out, int out_size) {
    const float* x   = (const float*)d_in[0];
    const float* qt  = (const float*)d_in[1];
    const float* ipw = (const float*)d_in[2];
    const float* ipb = (const float*)d_in[3];
    const float* opw = (const float*)d_in[4];
    const float* opb = (const float*)d_in[5];
    const float* lng = (const float*)d_in[6];
    const float* lnb = (const float*)d_in[7];
    float* out = (float*)d_out;

    float *pq, *pkv, *pctx, *py;
    cudaGetSymbolAddress((void**)&pq,  g_q);
    cudaGetSymbolAddress((void**)&pkv, g_kv);
    cudaGetSymbolAddress((void**)&pctx, g_ctx);
    cudaGetSymbolAddress((void**)&py,  g_y);

    // 1) q projection (scale 1/sqrt(64) baked in): [256,512] = qt @ Wq^T + bq
    gemm_kernel<<<dim3(4, 2), 256>>>(qt, ipw, 0, ipb, 0.125f, nullptr,
                                     pq, TDIM, CDIM, CDIM);
    // 2) kv projection: [65536,1024] = x @ [Wk;Wv]^T + [bk;bv]
    gemm_kernel<<<dim3(8, 512), 256>>>(x, ipw, CDIM, ipb + CDIM, 1.0f, nullptr,
                                       pkv, BATCH * SEQK, 2 * CDIM, CDIM);
    // 3) fused attention -> ctx
    attn_kernel<<<dim3(TDIM / 64, HEADS, BATCH), 256>>>(pq, pkv, pctx);
    // 4) out projection + residual: y = ctx @ Wo^T + bo + queries
    gemm_kernel<<<dim3(4, 16), 256>>>(pctx, opw, 0, opb, 1.0f, qt,
                                      py, BATCH * TDIM, CDIM, CDIM);
    // 5) layernorm -> out
    ln_kernel<<<BATCH * TDIM, 256>>>(py, lng, lnb, out);
}

// round 5
// speedup vs baseline: 1.4872x; 1.4872x over previous
#include <cuda_runtime.h>
#include <cstdint>
#include <cstddef>

// Problem constants
#define BATCH 8
#define SEQK  8192
#define CDIM  512
#define TDIM  256
#define HEADS 8
#define DH    64

// ---------------- scratch (device globals; no allocation allowed) -----------
__device__ float g_q[TDIM * CDIM];                                  // scaled q
__device__ float g_kv[(size_t)BATCH * SEQK * 2 * CDIM];             // k|v, 268MB
__device__ float g_ctx[(size_t)BATCH * TDIM * CDIM];                // attn out
__device__ float g_y[(size_t)BATCH * TDIM * CDIM];                  // pre-LN

// ---------------- packed fp32x2 helpers (FFMA2 path, sm_100+) ---------------
__device__ __forceinline__ unsigned long long pk2(float a, float b) {
    unsigned long long r;
    asm("mov.b64 %0, {%1, %2};" : "=l"(r) : "f"(a), "f"(b));
    return r;
}
__device__ __forceinline__ void fma2(unsigned long long& d,
                                     unsigned long long a, unsigned long long b) {
    asm("fma.rn.f32x2 %0, %1, %2, %0;" : "+l"(d) : "l"(a), "l"(b));
}
__device__ __forceinline__ void mul2(unsigned long long& d, unsigned long long a) {
    asm("mul.rn.f32x2 %0, %0, %1;" : "+l"(d) : "l"(a));
}
__device__ __forceinline__ float2 up2(unsigned long long v) {
    float lo, hi;
    asm("mov.b64 {%0, %1}, %2;" : "=f"(lo), "=f"(hi) : "l"(v));
    return make_float2(lo, hi);
}

// ---------------- tf32 mma.sync helpers (baseline PTX, sm_80+) --------------
__device__ __forceinline__ uint32_t f2tf(float f) {
    uint32_t r;
    asm("cvt.rna.tf32.f32 %0, %1;" : "=r"(r) : "f"(f));
    return r;
}
__device__ __forceinline__ void mma_tf32(float* c, const uint32_t* a,
                                         const uint32_t* b) {
    asm volatile(
        "mma.sync.aligned.m16n8k8.row.col.f32.tf32.tf32.f32 "
        "{%0,%1,%2,%3}, {%4,%5,%6,%7}, {%8,%9}, {%0,%1,%2,%3};"
        : "+f"(c[0]), "+f"(c[1]), "+f"(c[2]), "+f"(c[3])
        : "r"(a[0]), "r"(a[1]), "r"(a[2]), "r"(a[3]), "r"(b[0]), "r"(b[1]));
}

// ---------------- kv projection via mma.sync tf32 ----------------------------
// Out[m, n] = sum_k A[m,k] * W[n,k] + bias[n]
// A = x [65536, 512]; W = ipw rows 512..1535 (passed pre-offset) [1024, 512].
// CTA tile 128x128, K-chunk 16, double-buffered swizzled smem, 8 warps (2x4).
__global__ void __launch_bounds__(256)
kv_gemm_mma(const float* __restrict__ A, const float* __restrict__ W,
            const float* __restrict__ bias, float* __restrict__ Out)
{
    __shared__ uint32_t sA[2][128 * 16];
    __shared__ uint32_t sB[2][128 * 16];

    const int tid  = threadIdx.x;
    const int lane = tid & 31;
    const int warp = tid >> 5;
    const int wm   = warp >> 2;          // 0..1  (64-row slab)
    const int wn   = warp & 3;           // 0..3  (32-col slab)
    const int m0   = blockIdx.y * 128;
    const int n0   = blockIdx.x * 128;

    const int lr = tid >> 2;             // 0..63 (rows lr, lr+64)
    const int lk = (tid & 3) * 4;        // 0,4,8,12

    const float* Ag0 = A + (size_t)(m0 + lr) * CDIM + lk;
    const float* Ag1 = A + (size_t)(m0 + lr + 64) * CDIM + lk;
    const float* Bg0 = W + (size_t)(n0 + lr) * CDIM + lk;
    const float* Bg1 = W + (size_t)(n0 + lr + 64) * CDIM + lk;

    // swizzled store of one float4 at (row, lk..lk+3): pos = row*16 + ((lk+i)^c)
    auto sts4 = [&](uint32_t* sm, int r, float4 v) {
        const int c = 2 * (r & 7);
        const int base = r * 16 + (lk ^ (c & 12));
        const int o = c & 2;
        sm[base + o]       = f2tf(v.x);
        sm[base + o + 1]   = f2tf(v.y);
        sm[base + (2 - o)]     = f2tf(v.z);
        sm[base + (2 - o) + 1] = f2tf(v.w);
    };

    float acc[4][4][4];
#pragma unroll
    for (int i = 0; i < 4; i++)
#pragma unroll
        for (int j = 0; j < 4; j++)
#pragma unroll
            for (int t = 0; t < 4; t++) acc[i][j][t] = 0.0f;

    // prologue: tile 0
    {
        float4 a0 = *(const float4*)Ag0;
        float4 a1 = *(const float4*)Ag1;
        float4 b0 = *(const float4*)Bg0;
        float4 b1 = *(const float4*)Bg1;
        sts4(sA[0], lr, a0); sts4(sA[0], lr + 64, a1);
        sts4(sB[0], lr, b0); sts4(sB[0], lr + 64, b1);
    }
    __syncthreads();

    const int q  = lane >> 2;            // 0..7
    const int kk = lane & 3;             // 0..3
    const int cx = 2 * q;

    const int NIT = CDIM / 16;           // 32
    for (int it = 0; it < NIT; it++) {
        const int buf = it & 1;
        float4 ra0, ra1, rb0, rb1;
        if (it + 1 < NIT) {
            const int ko = (it + 1) * 16;
            ra0 = *(const float4*)(Ag0 + ko);
            ra1 = *(const float4*)(Ag1 + ko);
            rb0 = *(const float4*)(Bg0 + ko);
            rb1 = *(const float4*)(Bg1 + ko);
        }
        const uint32_t* sAb = sA[buf];
        const uint32_t* sBb = sB[buf];
#pragma unroll
        for (int ks = 0; ks < 2; ks++) {
            const int ka = ((ks << 3) + kk) ^ cx;
            const int kb = ka ^ 4;
            uint32_t af[4][4], bf[4][2];
#pragma unroll
            for (int mt = 0; mt < 4; mt++) {
                const int rb_ = (wm * 64 + mt * 16 + q) * 16;
                af[mt][0] = sAb[rb_ + ka];
                af[mt][1] = sAb[rb_ + 128 + ka];
                af[mt][2] = sAb[rb_ + kb];
                af[mt][3] = sAb[rb_ + 128 + kb];
            }
#pragma unroll
            for (int nt = 0; nt < 4; nt++) {
                const int rn = (wn * 32 + nt * 8 + q) * 16;
                bf[nt][0] = sBb[rn + ka];
                bf[nt][1] = sBb[rn + kb];
            }
#pragma unroll
            for (int mt = 0; mt < 4; mt++)
#pragma unroll
                for (int nt = 0; nt < 4; nt++)
                    mma_tf32(acc[mt][nt], af[mt], bf[nt]);
        }
        if (it + 1 < NIT) {
            const int nb = buf ^ 1;
            sts4(sA[nb], lr, ra0); sts4(sA[nb], lr + 64, ra1);
            sts4(sB[nb], lr, rb0); sts4(sB[nb], lr + 64, rb1);
            __syncthreads();
        }
    }

    // epilogue: c0/c1 -> (row q, cols 2kk,2kk+1); c2/c3 -> row q+8
#pragma unroll
    for (int mt = 0; mt < 4; mt++) {
        const int m = m0 + wm * 64 + mt * 16 + q;
#pragma unroll
        for (int nt = 0; nt < 4; nt++) {
            const int n = n0 + wn * 32 + nt * 8 + 2 * kk;
            const float bx = bias[n], by = bias[n + 1];
            float2 o0 = make_float2(acc[mt][nt][0] + bx, acc[mt][nt][1] + by);
            float2 o1 = make_float2(acc[mt][nt][2] + bx, acc[mt][nt][3] + by);
            *(float2*)(Out + (size_t)m * (2 * CDIM) + n) = o0;
            *(float2*)(Out + (size_t)(m + 8) * (2 * CDIM) + n) = o1;
        }
    }
}

// ---------------- generic tiled GEMM (fp32/FFMA2) — small GEMMs only ---------
__global__ void __launch_bounds__(256, 2)
gemm_kernel(const float* __restrict__ A,
            const float* __restrict__ W, int nOff,
            const float* __restrict__ bias,
            float alpha,
            const float* __restrict__ resid,
            float* __restrict__ Out,
            int M, int N, int Kd)
{
    __shared__ float sA[2][8][128];
    __shared__ float sB[2][8][128];

    const int tid = threadIdx.x;
    const int tm  = tid >> 4;
    const int tn  = tid & 15;
    const int m0  = blockIdx.y * 128;
    const int n0  = blockIdx.x * 128;
    const int lr  = tid >> 1;
    const int lq  = tid & 1;

    const float* Aload = A + (size_t)(m0 + lr) * Kd + lq * 4;
    const float* Wload = W + (size_t)(n0 + lr + nOff) * Kd + lq * 4;

    unsigned long long acc[8][4];
#pragma unroll
    for (int i = 0; i < 8; i++)
#pragma unroll
        for (int j = 0; j < 4; j++) acc[i][j] = 0ull;

    {
        float4 av = *(const float4*)(Aload);
        sA[0][lq*4+0][lr] = av.x; sA[0][lq*4+1][lr] = av.y;
        sA[0][lq*4+2][lr] = av.z; sA[0][lq*4+3][lr] = av.w;
        float4 bv = *(const float4*)(Wload);
        sB[0][lq*4+0][lr] = bv.x; sB[0][lq*4+1][lr] = bv.y;
        sB[0][lq*4+2][lr] = bv.z; sB[0][lq*4+3][lr] = bv.w;
    }
    __syncthreads();

    const int nPan = Kd >> 3;
    for (int p = 0; p < nPan; p++) {
        const int buf = p & 1;
        if (p + 1 < nPan) {
            const int nb = buf ^ 1;
            float4 av = *(const float4*)(Aload + (p + 1) * 8);
            float4 bv = *(const float4*)(Wload + (p + 1) * 8);
            sA[nb][lq*4+0][lr] = av.x; sA[nb][lq*4+1][lr] = av.y;
            sA[nb][lq*4+2][lr] = av.z; sA[nb][lq*4+3][lr] = av.w;
            sB[nb][lq*4+0][lr] = bv.x; sB[nb][lq*4+1][lr] = bv.y;
            sB[nb][lq*4+2][lr] = bv.z; sB[nb][lq*4+3][lr] = bv.w;
        }
#pragma unroll
        for (int kk = 0; kk < 8; kk++) {
            float4 a0 = *(const float4*)&sA[buf][kk][tm*8];
            float4 a1 = *(const float4*)&sA[buf][kk][tm*8+4];
            float4 b0 = *(const float4*)&sB[buf][kk][tn*8];
            float4 b1 = *(const float4*)&sB[buf][kk][tn*8+4];
            unsigned long long bp0 = pk2(b0.x, b0.y);
            unsigned long long bp1 = pk2(b0.z, b0.w);
            unsigned long long bp2 = pk2(b1.x, b1.y);
            unsigned long long bp3 = pk2(b1.z, b1.w);
            float ra[8] = {a0.x,a0.y,a0.z,a0.w,a1.x,a1.y,a1.z,a1.w};
#pragma unroll
            for (int i = 0; i < 8; i++) {
                unsigned long long ap = pk2(ra[i], ra[i]);
                fma2(acc[i][0], ap, bp0);
                fma2(acc[i][1], ap, bp1);
                fma2(acc[i][2], ap, bp2);
                fma2(acc[i][3], ap, bp3);
            }
        }
        __syncthreads();
    }

#pragma unroll
    for (int i = 0; i < 8; i++) {
        const int m = m0 + tm * 8 + i;
        const float* rrow = resid ? (resid + (size_t)(m & (TDIM - 1)) * N) : nullptr;
#pragma unroll
        for (int jp = 0; jp < 2; jp++) {
            const int n = n0 + tn * 8 + jp * 4;
            float2 v0 = up2(acc[i][jp*2+0]);
            float2 v1 = up2(acc[i][jp*2+1]);
            float4 o;
            o.x = (v0.x + bias[n+0]) * alpha;
            o.y = (v0.y + bias[n+1]) * alpha;
            o.z = (v1.x + bias[n+2]) * alpha;
            o.w = (v1.y + bias[n+3]) * alpha;
            if (rrow) { o.x += rrow[n+0]; o.y += rrow[n+1]; o.z += rrow[n+2]; o.w += rrow[n+3]; }
            *(float4*)(Out + (size_t)m * N + n) = o;
        }
    }
}

// ---------------- fused attention (fp32/FFMA2, known-good) ------------------
__global__ void __launch_bounds__(256, 2)
attn_kernel(const float* __restrict__ q,
            const float* __restrict__ kv,
            float* __restrict__ ctx)
{
    __shared__ float sQt[64 * 64];
    __shared__ float sKS[64 * 64];
    __shared__ float sV [64 * 64];

    const int tid = threadIdx.x;
    const int ty = tid >> 4, tx = tid & 15;
    const int t0 = blockIdx.x * 64;
    const int h  = blockIdx.y;
    const int b  = blockIdx.z;

    {
        const int tok = tid >> 2, fq = tid & 3;
        const float* qrow = q + (size_t)(t0 + tok) * CDIM + h * DH;
#pragma unroll
        for (int i = 0; i < 4; i++) {
            const int d4 = fq + i * 4;
            float4 v = *(const float4*)(qrow + d4 * 4);
            sQt[(d4*4+0)*64 + tok] = v.x;
            sQt[(d4*4+1)*64 + tok] = v.y;
            sQt[(d4*4+2)*64 + tok] = v.z;
            sQt[(d4*4+3)*64 + tok] = v.w;
        }
    }

    float mst[4], lst[4];
    unsigned long long acc[4][2];
#pragma unroll
    for (int i = 0; i < 4; i++) {
        mst[i] = -1e30f; lst[i] = 0.0f;
        acc[i][0] = 0ull; acc[i][1] = 0ull;
    }

    const float* kvbase = kv + (size_t)b * SEQK * (2 * CDIM) + h * DH;

    for (int kc = 0; kc < SEQK / 64; kc++) {
        {
            const int tok = tid >> 2, fq = tid & 3;
            const float* krow = kvbase + (size_t)(kc * 64 + tok) * (2 * CDIM);
#pragma unroll
            for (int i = 0; i < 4; i++) {
                const int d4 = fq + i * 4;
                float4 kvv = *(const float4*)(krow + d4 * 4);
                sKS[(d4*4+0)*64 + tok] = kvv.x;
                sKS[(d4*4+1)*64 + tok] = kvv.y;
                sKS[(d4*4+2)*64 + tok] = kvv.z;
                sKS[(d4*4+3)*64 + tok] = kvv.w;
                float4 vvv = *(const float4*)(krow + CDIM + d4 * 4);
                *(float4*)(sV + tok * 64 + d4 * 4) = vvv;
            }
        }
        __syncthreads();

        unsigned long long s2[4][2];
#pragma unroll
        for (int i = 0; i < 4; i++) { s2[i][0] = 0ull; s2[i][1] = 0ull; }
#pragma unroll 8
        for (int d = 0; d < 64; d++) {
            float4 qv  = *(const float4*)&sQt[d * 64 + ty * 4];
            float4 kk4 = *(const float4*)&sKS[d * 64 + tx * 4];
            unsigned long long k01 = pk2(kk4.x, kk4.y);
            unsigned long long k23 = pk2(kk4.z, kk4.w);
            unsigned long long q0 = pk2(qv.x, qv.x);
            unsigned long long q1 = pk2(qv.y, qv.y);
            unsigned long long q2 = pk2(qv.z, qv.z);
            unsigned long long q3 = pk2(qv.w, qv.w);
            fma2(s2[0][0], q0, k01); fma2(s2[0][1], q0, k23);
            fma2(s2[1][0], q1, k01); fma2(s2[1][1], q1, k23);
            fma2(s2[2][0], q2, k01); fma2(s2[2][1], q2, k23);
            fma2(s2[3][0], q3, k01); fma2(s2[3][1], q3, k23);
        }

        float p[4][4];
#pragma unroll
        for (int i = 0; i < 4; i++) {
            float2 sa = up2(s2[i][0]);
            float2 sb = up2(s2[i][1]);
            float rmax = fmaxf(fmaxf(sa.x, sa.y), fmaxf(sb.x, sb.y));
            rmax = fmaxf(rmax, __shfl_xor_sync(0xffffffffu, rmax, 1));
            rmax = fmaxf(rmax, __shfl_xor_sync(0xffffffffu, rmax, 2));
            rmax = fmaxf(rmax, __shfl_xor_sync(0xffffffffu, rmax, 4));
            rmax = fmaxf(rmax, __shfl_xor_sync(0xffffffffu, rmax, 8));
            float mnew = fmaxf(mst[i], rmax);
            float al = __expf(mst[i] - mnew);
            p[i][0] = __expf(sa.x - mnew);
            p[i][1] = __expf(sa.y - mnew);
            p[i][2] = __expf(sb.x - mnew);
            p[i][3] = __expf(sb.y - mnew);
            float rs = (p[i][0] + p[i][1]) + (p[i][2] + p[i][3]);
            rs += __shfl_xor_sync(0xffffffffu, rs, 1);
            rs += __shfl_xor_sync(0xffffffffu, rs, 2);
            rs += __shfl_xor_sync(0xffffffffu, rs, 4);
            rs += __shfl_xor_sync(0xffffffffu, rs, 8);
            lst[i] = lst[i] * al + rs;
            mst[i] = mnew;
            unsigned long long al2 = pk2(al, al);
            mul2(acc[i][0], al2);
            mul2(acc[i][1], al2);
        }
        __syncthreads();

#pragma unroll
        for (int j = 0; j < 4; j++) {
            const int kr = tx * 4 + j;
            const int sw = kr & 31;
#pragma unroll
            for (int i = 0; i < 4; i++)
                sKS[kr * 64 + ((ty * 4 + i) ^ sw)] = p[i][j];
        }
        __syncthreads();

#pragma unroll 8
        for (int kkx = 0; kkx < 64; kkx++) {
            float4 vv = *(const float4*)&sV[kkx * 64 + tx * 4];
            unsigned long long v01 = pk2(vv.x, vv.y);
            unsigned long long v23 = pk2(vv.z, vv.w);
            const int sw = kkx & 31;
            const int base = kkx * 64;
            float p0 = sKS[base + ((ty*4+0) ^ sw)];
            float p1 = sKS[base + ((ty*4+1) ^ sw)];
            float p2 = sKS[base + ((ty*4+2) ^ sw)];
            float p3 = sKS[base + ((ty*4+3) ^ sw)];
            fma2(acc[0][0], pk2(p0,p0), v01); fma2(acc[0][1], pk2(p0,p0), v23);
            fma2(acc[1][0], pk2(p1,p1), v01); fma2(acc[1][1], pk2(p1,p1), v23);
            fma2(acc[2][0], pk2(p2,p2), v01); fma2(acc[2][1], pk2(p2,p2), v23);
            fma2(acc[3][0], pk2(p3,p3), v01); fma2(acc[3][1], pk2(p3,p3), v23);
        }
        __syncthreads();
    }

#pragma unroll
    for (int i = 0; i < 4; i++) {
        const float inv = 1.0f / lst[i];
        float2 a0 = up2(acc[i][0]);
        float2 a1 = up2(acc[i][1]);
        float4 o = make_float4(a0.x * inv, a0.y * inv, a1.x * inv, a1.y * inv);
        const int t = t0 + ty * 4 + i;
        *(float4*)(ctx + (size_t)(b * TDIM + t) * CDIM + h * DH + tx * 4) = o;
    }
}

// ---------------- LayerNorm over C=512 -------------------------------------
__global__ void __launch_bounds__(256)
ln_kernel(const float* __restrict__ y, const float* __restrict__ gamma,
          const float* __restrict__ beta, float* __restrict__ out)
{
    __shared__ float2 sred[8];
    const int row = blockIdx.x;
    const int tid = threadIdx.x;
    const float* yr = y + (size_t)row * CDIM;
    float2 v = *(const float2*)(yr + tid * 2);
    float s1 = v.x + v.y;
    float s2 = v.x * v.x + v.y * v.y;
#pragma unroll
    for (int o = 16; o > 0; o >>= 1) {
        s1 += __shfl_xor_sync(0xffffffffu, s1, o);
        s2 += __shfl_xor_sync(0xffffffffu, s2, o);
    }
    if ((tid & 31) == 0) sred[tid >> 5] = make_float2(s1, s2);
    __syncthreads();
    float t1 = 0.f, t2 = 0.f;
#pragma unroll
    for (int i = 0; i < 8; i++) { t1 += sred[i].x; t2 += sred[i].y; }
    const float mean = t1 * (1.0f / CDIM);
    const float var  = t2 * (1.0f / CDIM) - mean * mean;
    const float rstd = rsqrtf(var + 1e-5f);
    const int c = tid * 2;
    float2 g = *(const float2*)(gamma + c);
    float2 be = *(const float2*)(beta + c);
    float2 o;
    o.x = (v.x - mean) * rstd * g.x + be.x;
    o.y = (v.y - mean) * rstd * g.y + be.y;
    *(float2*)(out + (size_t)row * CDIM + c) = o;
}

// ---------------- launch ----------------------------------------------------
extern "C" void kernel_launch(void* const* d_in, const int* in_sizes, int n_in,
                              void* d_out, int out_size) {
    const float* x   = (const float*)d_in[0];
    const float* qt  = (const float*)d_in[1];
    const float* ipw = (const float*)d_in[2];
    const float* ipb = (const float*)d_in[3];
    const float* opw = (const float*)d_in[4];
    const float* opb = (const float*)d_in[5];
    const float* lng = (const float*)d_in[6];
    const float* lnb = (const float*)d_in[7];
    float* out = (float*)d_out;

    float *pq, *pkv, *pctx, *py;
    cudaGetSymbolAddress((void**)&pq,  g_q);
    cudaGetSymbolAddress((void**)&pkv, g_kv);
    cudaGetSymbolAddress((void**)&pctx, g_ctx);
    cudaGetSymbolAddress((void**)&py,  g_y);

    // 1) q projection (scale 1/sqrt(64) baked in)
    gemm_kernel<<<dim3(4, 2), 256>>>(qt, ipw, 0, ipb, 0.125f, nullptr,
                                     pq, TDIM, CDIM, CDIM);
    // 2) kv projection via mma.sync tf32: [65536,1024] = x @ [Wk;Wv]^T + [bk;bv]
    kv_gemm_mma<<<dim3(8, 512), 256>>>(x, ipw + CDIM * CDIM, ipb + CDIM, pkv);
    // 3) fused attention -> ctx
    attn_kernel<<<dim3(TDIM / 64, HEADS, BATCH), 256>>>(pq, pkv, pctx);
    // 4) out projection + residual
    gemm_kernel<<<dim3(4, 16), 256>>>(pctx, opw, 0, opb, 1.0f, qt,
                                      py, BATCH * TDIM, CDIM, CDIM);
    // 5) layernorm -> out
    ln_kernel<<<BATCH * TDIM, 256>>>(py, lng, lnb, out);
}

// round 11
// speedup vs baseline: 2.7108x; 1.8227x over previous
#include <cuda_runtime.h>
#include <cstdint>
#include <cstddef>

// Problem constants
#define BATCH 8
#define SEQK  8192
#define CDIM  512
#define TDIM  256
#define HEADS 8
#define DH    64

// ---------------- scratch (device globals; no allocation allowed) -----------
__device__ float g_q[TDIM * CDIM];                                  // scaled q
__device__ float g_kv[(size_t)BATCH * SEQK * 2 * CDIM];             // k|v, 268MB
__device__ float g_ctx[(size_t)BATCH * TDIM * CDIM];                // attn out
__device__ float g_y[(size_t)BATCH * TDIM * CDIM];                  // pre-LN

// ---------------- packed fp32x2 helpers (FFMA2 path, sm_100+) ---------------
__device__ __forceinline__ unsigned long long pk2(float a, float b) {
    unsigned long long r;
    asm("mov.b64 %0, {%1, %2};" : "=l"(r) : "f"(a), "f"(b));
    return r;
}
__device__ __forceinline__ void fma2(unsigned long long& d,
                                     unsigned long long a, unsigned long long b) {
    asm("fma.rn.f32x2 %0, %1, %2, %0;" : "+l"(d) : "l"(a), "l"(b));
}
__device__ __forceinline__ float2 up2(unsigned long long v) {
    float lo, hi;
    asm("mov.b64 {%0, %1}, %2;" : "=f"(lo), "=f"(hi) : "l"(v));
    return make_float2(lo, hi);
}

// ---------------- tf32 mma.sync helpers (baseline PTX, sm_80+) --------------
__device__ __forceinline__ uint32_t f2tf(float f) {
    uint32_t r;
    asm("cvt.rna.tf32.f32 %0, %1;" : "=r"(r) : "f"(f));
    return r;
}
__device__ __forceinline__ void mma_tf32(float* c, const uint32_t* a,
                                         const uint32_t* b) {
    asm volatile(
        "mma.sync.aligned.m16n8k8.row.col.f32.tf32.tf32.f32 "
        "{%0,%1,%2,%3}, {%4,%5,%6,%7}, {%8,%9}, {%0,%1,%2,%3};"
        : "+f"(c[0]), "+f"(c[1]), "+f"(c[2]), "+f"(c[3])
        : "r"(a[0]), "r"(a[1]), "r"(a[2]), "r"(a[3]), "r"(b[0]), "r"(b[1]));
}

// swizzled index into a [rows x 64] uint32 smem tile (conflict-free frag LDS)
#define PSW(r, c) (((r) << 6) + (((((c) >> 2) ^ ((r) & 7))) << 2) + ((c) & 3))

// ---------------- kv projection via mma.sync tf32 (unchanged, passing) ------
__global__ void __launch_bounds__(256)
kv_gemm_mma(const float* __restrict__ A, const float* __restrict__ W,
            const float* __restrict__ bias, float* __restrict__ Out)
{
    __shared__ uint32_t sA[2][128 * 16];
    __shared__ uint32_t sB[2][128 * 16];

    const int tid  = threadIdx.x;
    const int lane = tid & 31;
    const int warp = tid >> 5;
    const int wm   = warp >> 2;
    const int wn   = warp & 3;
    const int m0   = blockIdx.y * 128;
    const int n0   = blockIdx.x * 128;

    const int lr = tid >> 2;
    const int lk = (tid & 3) * 4;

    const float* Ag0 = A + (size_t)(m0 + lr) * CDIM + lk;
    const float* Ag1 = A + (size_t)(m0 + lr + 64) * CDIM + lk;
    const float* Bg0 = W + (size_t)(n0 + lr) * CDIM + lk;
    const float* Bg1 = W + (size_t)(n0 + lr + 64) * CDIM + lk;

    auto sts4 = [&](uint32_t* sm, int r, float4 v) {
        const int c = 2 * (r & 7);
        const int base = r * 16 + (lk ^ (c & 12));
        const int o = c & 2;
        sm[base + o]       = f2tf(v.x);
        sm[base + o + 1]   = f2tf(v.y);
        sm[base + (2 - o)]     = f2tf(v.z);
        sm[base + (2 - o) + 1] = f2tf(v.w);
    };

    float acc[4][4][4];
#pragma unroll
    for (int i = 0; i < 4; i++)
#pragma unroll
        for (int j = 0; j < 4; j++)
#pragma unroll
            for (int t = 0; t < 4; t++) acc[i][j][t] = 0.0f;

    {
        float4 a0 = *(const float4*)Ag0;
        float4 a1 = *(const float4*)Ag1;
        float4 b0 = *(const float4*)Bg0;
        float4 b1 = *(const float4*)Bg1;
        sts4(sA[0], lr, a0); sts4(sA[0], lr + 64, a1);
        sts4(sB[0], lr, b0); sts4(sB[0], lr + 64, b1);
    }
    __syncthreads();

    const int q  = lane >> 2;
    const int kk = lane & 3;
    const int cx = 2 * q;

    const int NIT = CDIM / 16;
    for (int it = 0; it < NIT; it++) {
        const int buf = it & 1;
        float4 ra0, ra1, rb0, rb1;
        if (it + 1 < NIT) {
            const int ko = (it + 1) * 16;
            ra0 = *(const float4*)(Ag0 + ko);
            ra1 = *(const float4*)(Ag1 + ko);
            rb0 = *(const float4*)(Bg0 + ko);
            rb1 = *(const float4*)(Bg1 + ko);
        }
        const uint32_t* sAb = sA[buf];
        const uint32_t* sBb = sB[buf];
#pragma unroll
        for (int ks = 0; ks < 2; ks++) {
            const int ka = ((ks << 3) + kk) ^ cx;
            const int kb = ka ^ 4;
            uint32_t af[4][4], bf[4][2];
#pragma unroll
            for (int mt = 0; mt < 4; mt++) {
                const int rb_ = (wm * 64 + mt * 16 + q) * 16;
                af[mt][0] = sAb[rb_ + ka];
                af[mt][1] = sAb[rb_ + 128 + ka];
                af[mt][2] = sAb[rb_ + kb];
                af[mt][3] = sAb[rb_ + 128 + kb];
            }
#pragma unroll
            for (int nt = 0; nt < 4; nt++) {
                const int rn = (wn * 32 + nt * 8 + q) * 16;
                bf[nt][0] = sBb[rn + ka];
                bf[nt][1] = sBb[rn + kb];
            }
#pragma unroll
            for (int mt = 0; mt < 4; mt++)
#pragma unroll
                for (int nt = 0; nt < 4; nt++)
                    mma_tf32(acc[mt][nt], af[mt], bf[nt]);
        }
        if (it + 1 < NIT) {
            const int nb = buf ^ 1;
            sts4(sA[nb], lr, ra0); sts4(sA[nb], lr + 64, ra1);
            sts4(sB[nb], lr, rb0); sts4(sB[nb], lr + 64, rb1);
            __syncthreads();
        }
    }

#pragma unroll
    for (int mt = 0; mt < 4; mt++) {
        const int m = m0 + wm * 64 + mt * 16 + q;
#pragma unroll
        for (int nt = 0; nt < 4; nt++) {
            const int n = n0 + wn * 32 + nt * 8 + 2 * kk;
            const float bx = bias[n], by = bias[n + 1];
            float2 o0 = make_float2(acc[mt][nt][0] + bx, acc[mt][nt][1] + by);
            float2 o1 = make_float2(acc[mt][nt][2] + bx, acc[mt][nt][3] + by);
            *(float2*)(Out + (size_t)m * (2 * CDIM) + n) = o0;
            *(float2*)(Out + (size_t)(m + 8) * (2 * CDIM) + n) = o1;
        }
    }
}

// ---------------- flash attention via mma.sync tf32 --------------------------
// CTA = (128-query tile, head, batch); 8 warps x 16 query rows.
// smem (dynamic 64KB): sK[64x64] | sVt[64x64] | sP[128x64] (sP doubles as Q stage)
__global__ void __launch_bounds__(256)
attn_mma(const float* __restrict__ q, const float* __restrict__ kv,
         float* __restrict__ ctx)
{
    extern __shared__ uint32_t sm[];
    uint32_t* sK  = sm;           // 64*64
    uint32_t* sVt = sm + 4096;    // 64*64 (V transposed: [dh][key])
    uint32_t* sP  = sm + 8192;    // 128*64

    const int tid  = threadIdx.x;
    const int lane = tid & 31;
    const int w    = tid >> 5;
    const int qr   = lane >> 2;      // 0..7
    const int kk   = lane & 3;       // 0..3
    const int t0   = blockIdx.x * 128;
    const int h    = blockIdx.y;
    const int b    = blockIdx.z;
    const int r0   = w * 16 + qr;

    // stage Q tile (pre-scaled by 1/8 in q-proj) into sP, swizzled tf32
    {
        const int r  = tid >> 1;
        const int cb = (tid & 1) * 32;
        const float* qrow = q + (size_t)(t0 + r) * CDIM + h * DH + cb;
#pragma unroll
        for (int j = 0; j < 8; j++) {
            float4 v = *(const float4*)(qrow + j * 4);
            const int c4 = (((cb >> 2) + j) ^ (r & 7)) << 2;
            uint32_t* d = sP + r * 64 + c4;
            d[0] = f2tf(v.x); d[1] = f2tf(v.y); d[2] = f2tf(v.z); d[3] = f2tf(v.w);
        }
    }
    __syncthreads();

    // Q fragments live in registers for the whole kernel
    uint32_t qa[8][4];
#pragma unroll
    for (int ks = 0; ks < 8; ks++) {
        qa[ks][0] = sP[PSW(r0,     kk + 8 * ks)];
        qa[ks][1] = sP[PSW(r0 + 8, kk + 8 * ks)];
        qa[ks][2] = sP[PSW(r0,     kk + 4 + 8 * ks)];
        qa[ks][3] = sP[PSW(r0 + 8, kk + 4 + 8 * ks)];
    }
    // (the in-loop syncs order these reads before any P write to sP)

    float o[8][4];
#pragma unroll
    for (int nt = 0; nt < 8; nt++)
#pragma unroll
        for (int t = 0; t < 4; t++) o[nt][t] = 0.0f;
    float m0 = -1e30f, m1 = -1e30f, l0 = 0.0f, l1 = 0.0f;

    const float* kvb = kv + (size_t)b * SEQK * (2 * CDIM) + h * DH;
    const int kr = tid >> 2;         // 0..63 key row
    const int kq = tid & 3;          // 16-col group

    float4 kreg[4], vreg[4];
    {
        const float* krow = kvb + (size_t)kr * (2 * CDIM) + kq * 16;
#pragma unroll
        for (int j = 0; j < 4; j++) {
            kreg[j] = *(const float4*)(krow + j * 4);
            vreg[j] = *(const float4*)(krow + CDIM + j * 4);
        }
    }

    for (int c = 0; c < SEQK / 64; c++) {
        if (c) __syncthreads();      // prior chunk's mma reads done
        // STS K (swizzled uint4)
#pragma unroll
        for (int j = 0; j < 4; j++) {
            const int c4 = ((kq * 4 + j) ^ (kr & 7)) << 2;
            uint32_t* d = sK + kr * 64 + c4;
            d[0] = f2tf(kreg[j].x); d[1] = f2tf(kreg[j].y);
            d[2] = f2tf(kreg[j].z); d[3] = f2tf(kreg[j].w);
        }
        // STS V transposed (rotation over kq keeps banks distinct)
        {
            const float* vf = (const float*)vreg;
#pragma unroll
            for (int i = 0; i < 16; i++) {
                const int idx = (i + kq * 2) & 15;
                const int dd = kq * 16 + idx;
                sVt[PSW(dd, kr)] = f2tf(vf[idx]);
            }
        }
        // prefetch next chunk into registers (overlaps mma section)
        if (c + 1 < SEQK / 64) {
            const float* krow = kvb + (size_t)((c + 1) * 64 + kr) * (2 * CDIM) + kq * 16;
#pragma unroll
            for (int j = 0; j < 4; j++) {
                kreg[j] = *(const float4*)(krow + j * 4);
                vreg[j] = *(const float4*)(krow + CDIM + j * 4);
            }
        }
        __syncthreads();

        // S = Q K^T : rows r0,r0+8; cols = 64 keys (8 n-tiles)
        float sc[8][4];
#pragma unroll
        for (int nt = 0; nt < 8; nt++)
#pragma unroll
            for (int t = 0; t < 4; t++) sc[nt][t] = 0.0f;
#pragma unroll
        for (int ks = 0; ks < 8; ks++) {
#pragma unroll
            for (int nt = 0; nt < 8; nt++) {
                uint32_t bf[2];
                bf[0] = sK[PSW(nt * 8 + qr, kk + 8 * ks)];
                bf[1] = sK[PSW(nt * 8 + qr, kk + 4 + 8 * ks)];
                mma_tf32(sc[nt], qa[ks], bf);
            }
        }

        // online softmax over this chunk (quad lanes share a row)
        float mx0 = -1e30f, mx1 = -1e30f;
#pragma unroll
        for (int nt = 0; nt < 8; nt++) {
            mx0 = fmaxf(mx0, fmaxf(sc[nt][0], sc[nt][1]));
            mx1 = fmaxf(mx1, fmaxf(sc[nt][2], sc[nt][3]));
        }
        mx0 = fmaxf(mx0, __shfl_xor_sync(0xffffffffu, mx0, 1));
        mx0 = fmaxf(mx0, __shfl_xor_sync(0xffffffffu, mx0, 2));
        mx1 = fmaxf(mx1, __shfl_xor_sync(0xffffffffu, mx1, 1));
        mx1 = fmaxf(mx1, __shfl_xor_sync(0xffffffffu, mx1, 2));
        const float m0n = fmaxf(m0, mx0), m1n = fmaxf(m1, mx1);
        const float al0 = __expf(m0 - m0n), al1 = __expf(m1 - m1n);
        float s0 = 0.0f, s1 = 0.0f;
#pragma unroll
        for (int nt = 0; nt < 8; nt++) {
            sc[nt][0] = __expf(sc[nt][0] - m0n);
            sc[nt][1] = __expf(sc[nt][1] - m0n);
            sc[nt][2] = __expf(sc[nt][2] - m1n);
            sc[nt][3] = __expf(sc[nt][3] - m1n);
            s0 += sc[nt][0] + sc[nt][1];
            s1 += sc[nt][2] + sc[nt][3];
        }
        s0 += __shfl_xor_sync(0xffffffffu, s0, 1);
        s0 += __shfl_xor_sync(0xffffffffu, s0, 2);
        s1 += __shfl_xor_sync(0xffffffffu, s1, 1);
        s1 += __shfl_xor_sync(0xffffffffu, s1, 2);
        l0 = l0 * al0 + s0;  l1 = l1 * al1 + s1;
        m0 = m0n;  m1 = m1n;
#pragma unroll
        for (int nt = 0; nt < 8; nt++) {
            o[nt][0] *= al0; o[nt][1] *= al0;
            o[nt][2] *= al1; o[nt][3] *= al1;
        }

        // write P (tf32, swizzled) for the PV mma
#pragma unroll
        for (int nt = 0; nt < 8; nt++) {
            const int cb = nt * 8 + 2 * kk;
            sP[PSW(r0, cb)]         = f2tf(sc[nt][0]);
            sP[PSW(r0, cb + 1)]     = f2tf(sc[nt][1]);
            sP[PSW(r0 + 8, cb)]     = f2tf(sc[nt][2]);
            sP[PSW(r0 + 8, cb + 1)] = f2tf(sc[nt][3]);
        }
        __syncthreads();

        // O += P V  (contraction over 64 keys)
#pragma unroll
        for (int ks = 0; ks < 8; ks++) {
            uint32_t af[4];
            af[0] = sP[PSW(r0,     kk + 8 * ks)];
            af[1] = sP[PSW(r0 + 8, kk + 8 * ks)];
            af[2] = sP[PSW(r0,     kk + 4 + 8 * ks)];
            af[3] = sP[PSW(r0 + 8, kk + 4 + 8 * ks)];
#pragma unroll
            for (int nt = 0; nt < 8; nt++) {
                uint32_t bf[2];
                bf[0] = sVt[PSW(nt * 8 + qr, kk + 8 * ks)];
                bf[1] = sVt[PSW(nt * 8 + qr, kk + 4 + 8 * ks)];
                mma_tf32(o[nt], af, bf);
            }
        }
    }

    // epilogue: ctx = O / l
    const float i0 = 1.0f / l0, i1 = 1.0f / l1;
    float* crow0 = ctx + (size_t)(b * TDIM + t0 + r0) * CDIM + h * DH;
    float* crow1 = crow0 + (size_t)8 * CDIM;
#pragma unroll
    for (int nt = 0; nt < 8; nt++) {
        const int cb = nt * 8 + 2 * kk;
        *(float2*)(crow0 + cb) = make_float2(o[nt][0] * i0, o[nt][1] * i0);
        *(float2*)(crow1 + cb) = make_float2(o[nt][2] * i1, o[nt][3] * i1);
    }
}

// ---------------- generic tiled GEMM (fp32/FFMA2) — small GEMMs only ---------
__global__ void __launch_bounds__(256, 2)
gemm_kernel(const float* __restrict__ A,
            const float* __restrict__ W, int nOff,
            const float* __restrict__ bias,
            float alpha,
            const float* __restrict__ resid,
            float* __restrict__ Out,
            int M, int N, int Kd)
{
    __shared__ float sA[2][8][128];
    __shared__ float sB[2][8][128];

    const int tid = threadIdx.x;
    const int tm  = tid >> 4;
    const int tn  = tid & 15;
    const int m0  = blockIdx.y * 128;
    const int n0  = blockIdx.x * 128;
    const int lr  = tid >> 1;
    const int lq  = tid & 1;

    const float* Aload = A + (size_t)(m0 + lr) * Kd + lq * 4;
    const float* Wload = W + (size_t)(n0 + lr + nOff) * Kd + lq * 4;

    unsigned long long acc[8][4];
#pragma unroll
    for (int i = 0; i < 8; i++)
#pragma unroll
        for (int j = 0; j < 4; j++) acc[i][j] = 0ull;

    {
        float4 av = *(const float4*)(Aload);
        sA[0][lq*4+0][lr] = av.x; sA[0][lq*4+1][lr] = av.y;
        sA[0][lq*4+2][lr] = av.z; sA[0][lq*4+3][lr] = av.w;
        float4 bv = *(const float4*)(Wload);
        sB[0][lq*4+0][lr] = bv.x; sB[0][lq*4+1][lr] = bv.y;
        sB[0][lq*4+2][lr] = bv.z; sB[0][lq*4+3][lr] = bv.w;
    }
    __syncthreads();

    const int nPan = Kd >> 3;
    for (int p = 0; p < nPan; p++) {
        const int buf = p & 1;
        if (p + 1 < nPan) {
            const int nb = buf ^ 1;
            float4 av = *(const float4*)(Aload + (p + 1) * 8);
            float4 bv = *(const float4*)(Wload + (p + 1) * 8);
            sA[nb][lq*4+0][lr] = av.x; sA[nb][lq*4+1][lr] = av.y;
            sA[nb][lq*4+2][lr] = av.z; sA[nb][lq*4+3][lr] = av.w;
            sB[nb][lq*4+0][lr] = bv.x; sB[nb][lq*4+1][lr] = bv.y;
            sB[nb][lq*4+2][lr] = bv.z; sB[nb][lq*4+3][lr] = bv.w;
        }
#pragma unroll
        for (int kk = 0; kk < 8; kk++) {
            float4 a0 = *(const float4*)&sA[buf][kk][tm*8];
            float4 a1 = *(const float4*)&sA[buf][kk][tm*8+4];
            float4 b0 = *(const float4*)&sB[buf][kk][tn*8];
            float4 b1 = *(const float4*)&sB[buf][kk][tn*8+4];
            unsigned long long bp0 = pk2(b0.x, b0.y);
            unsigned long long bp1 = pk2(b0.z, b0.w);
            unsigned long long bp2 = pk2(b1.x, b1.y);
            unsigned long long bp3 = pk2(b1.z, b1.w);
            float ra[8] = {a0.x,a0.y,a0.z,a0.w,a1.x,a1.y,a1.z,a1.w};
#pragma unroll
            for (int i = 0; i < 8; i++) {
                unsigned long long ap = pk2(ra[i], ra[i]);
                fma2(acc[i][0], ap, bp0);
                fma2(acc[i][1], ap, bp1);
                fma2(acc[i][2], ap, bp2);
                fma2(acc[i][3], ap, bp3);
            }
        }
        __syncthreads();
    }

#pragma unroll
    for (int i = 0; i < 8; i++) {
        const int m = m0 + tm * 8 + i;
        const float* rrow = resid ? (resid + (size_t)(m & (TDIM - 1)) * N) : nullptr;
#pragma unroll
        for (int jp = 0; jp < 2; jp++) {
            const int n = n0 + tn * 8 + jp * 4;
            float2 v0 = up2(acc[i][jp*2+0]);
            float2 v1 = up2(acc[i][jp*2+1]);
            float4 o;
            o.x = (v0.x + bias[n+0]) * alpha;
            o.y = (v0.y + bias[n+1]) * alpha;
            o.z = (v1.x + bias[n+2]) * alpha;
            o.w = (v1.y + bias[n+3]) * alpha;
            if (rrow) { o.x += rrow[n+0]; o.y += rrow[n+1]; o.z += rrow[n+2]; o.w += rrow[n+3]; }
            *(float4*)(Out + (size_t)m * N + n) = o;
        }
    }
}

// ---------------- LayerNorm over C=512 -------------------------------------
__global__ void __launch_bounds__(256)
ln_kernel(const float* __restrict__ y, const float* __restrict__ gamma,
          const float* __restrict__ beta, float* __restrict__ out)
{
    __shared__ float2 sred[8];
    const int row = blockIdx.x;
    const int tid = threadIdx.x;
    const float* yr = y + (size_t)row * CDIM;
    float2 v = *(const float2*)(yr + tid * 2);
    float s1 = v.x + v.y;
    float s2 = v.x * v.x + v.y * v.y;
#pragma unroll
    for (int o = 16; o > 0; o >>= 1) {
        s1 += __shfl_xor_sync(0xffffffffu, s1, o);
        s2 += __shfl_xor_sync(0xffffffffu, s2, o);
    }
    if ((tid & 31) == 0) sred[tid >> 5] = make_float2(s1, s2);
    __syncthreads();
    float t1 = 0.f, t2 = 0.f;
#pragma unroll
    for (int i = 0; i < 8; i++) { t1 += sred[i].x; t2 += sred[i].y; }
    const float mean = t1 * (1.0f / CDIM);
    const float var  = t2 * (1.0f / CDIM) - mean * mean;
    const float rstd = rsqrtf(var + 1e-5f);
    const int c = tid * 2;
    float2 g = *(const float2*)(gamma + c);
    float2 be = *(const float2*)(beta + c);
    float2 o;
    o.x = (v.x - mean) * rstd * g.x + be.x;
    o.y = (v.y - mean) * rstd * g.y + be.y;
    *(float2*)(out + (size_t)row * CDIM + c) = o;
}

// ---------------- launch ----------------------------------------------------
extern "C" void kernel_launch(void* const* d_in, const int* in_sizes, int n_in,
                              void* d_out, int out_size) {
    const float* x   = (const float*)d_in[0];
    const float* qt  = (const float*)d_in[1];
    const float* ipw = (const float*)d_in[2];
    const float* ipb = (const float*)d_in[3];
    const float* opw = (const float*)d_in[4];
    const float* opb = (const float*)d_in[5];
    const float* lng = (const float*)d_in[6];
    const float* lnb = (const float*)d_in[7];
    float* out = (float*)d_out;

    float *pq, *pkv, *pctx, *py;
    cudaGetSymbolAddress((void**)&pq,  g_q);
    cudaGetSymbolAddress((void**)&pkv, g_kv);
    cudaGetSymbolAddress((void**)&pctx, g_ctx);
    cudaGetSymbolAddress((void**)&py,  g_y);

    cudaFuncSetAttribute(attn_mma, cudaFuncAttributeMaxDynamicSharedMemorySize,
                         65536);

    // 1) q projection (scale 1/sqrt(64) baked in)
    gemm_kernel<<<dim3(4, 2), 256>>>(qt, ipw, 0, ipb, 0.125f, nullptr,
                                     pq, TDIM, CDIM, CDIM);
    // 2) kv projection via mma.sync tf32
    kv_gemm_mma<<<dim3(8, 512), 256>>>(x, ipw + CDIM * CDIM, ipb + CDIM, pkv);
    // 3) fused flash attention via mma.sync tf32 -> ctx
    attn_mma<<<dim3(TDIM / 128, HEADS, BATCH), 256, 65536>>>(pq, pkv, pctx);
    // 4) out projection + residual
    gemm_kernel<<<dim3(4, 16), 256>>>(pctx, opw, 0, opb, 1.0f, qt,
                                      py, BATCH * TDIM, CDIM, CDIM);
    // 5) layernorm -> out
    ln_kernel<<<BATCH * TDIM, 256>>>(py, lng, lnb, out);
}

// round 12
// speedup vs baseline: 2.8357x; 1.0461x over previous
#include <cuda_runtime.h>
#include <cstdint>
#include <cstddef>

// Problem constants
#define BATCH 8
#define SEQK  8192
#define CDIM  512
#define TDIM  256
#define HEADS 8
#define DH    64

// ---------------- scratch (device globals; no allocation allowed) -----------
__device__ float g_q[TDIM * CDIM];                                  // scaled q
__device__ float g_kv[(size_t)BATCH * SEQK * 2 * CDIM];             // k|v, 268MB
__device__ float g_ctx[(size_t)BATCH * TDIM * CDIM];                // attn out
__device__ float g_y[(size_t)BATCH * TDIM * CDIM];                  // pre-LN

// ---------------- tf32 mma.sync helpers (baseline PTX, sm_80+) --------------
__device__ __forceinline__ uint32_t f2tf(float f) {
    uint32_t r;
    asm("cvt.rna.tf32.f32 %0, %1;" : "=r"(r) : "f"(f));
    return r;
}
__device__ __forceinline__ void mma_tf32(float* c, const uint32_t* a,
                                         const uint32_t* b) {
    asm volatile(
        "mma.sync.aligned.m16n8k8.row.col.f32.tf32.tf32.f32 "
        "{%0,%1,%2,%3}, {%4,%5,%6,%7}, {%8,%9}, {%0,%1,%2,%3};"
        : "+f"(c[0]), "+f"(c[1]), "+f"(c[2]), "+f"(c[3])
        : "r"(a[0]), "r"(a[1]), "r"(a[2]), "r"(a[3]), "r"(b[0]), "r"(b[1]));
}

// swizzled index into a [rows x 64] uint32 smem tile (conflict-free frag LDS)
#define PSW(r, c) (((r) << 6) + (((((c) >> 2) ^ ((r) & 7))) << 2) + ((c) & 3))

// ---------------- unified tf32 GEMM: Out = (A @ W^T + bias)*alpha + resid ----
// CTA tile 128 (M) x 256 (N), K = CDIM = 512 in chunks of 16.
// 8 warps: wm = warp>>2 (2 x 64 rows), wn = warp&3 (4 x 64 cols).
// Element (r, k) of a chunk stored at smem[r*16 + (k ^ (2*(r&7)))].
__global__ void __launch_bounds__(256)
gemm_tf32(const float* __restrict__ A, const float* __restrict__ W,
          const float* __restrict__ bias, float alpha,
          const float* __restrict__ resid,    // row m & 255, len CDIM (or null)
          float* __restrict__ Out, int M, int outStride)
{
    __shared__ uint32_t sA[2][128 * 16];   // 16 KB
    __shared__ uint32_t sB[2][256 * 16];   // 32 KB

    const int tid  = threadIdx.x;
    const int lane = tid & 31;
    const int warp = tid >> 5;
    const int wm   = warp >> 2;          // 0..1
    const int wn   = warp & 3;           // 0..3
    const int m0   = blockIdx.y * 128;
    const int n0   = blockIdx.x * 256;

    const int lr = tid >> 2;             // 0..63
    const int lk = (tid & 3) * 4;        // 0,4,8,12

    const float* Ag0 = A + (size_t)(m0 + lr) * CDIM + lk;
    const float* Ag1 = Ag0 + (size_t)64 * CDIM;
    const float* Bg0 = W + (size_t)(n0 + lr) * CDIM + lk;
    const float* Bg1 = Bg0 + (size_t)64 * CDIM;
    const float* Bg2 = Bg0 + (size_t)128 * CDIM;
    const float* Bg3 = Bg0 + (size_t)192 * CDIM;

    auto sts4 = [&](uint32_t* sm, int r, float4 v) {
        const int c = 2 * (r & 7);
        const int base = r * 16 + (lk ^ (c & 12));
        const int o = c & 2;
        sm[base + o]           = f2tf(v.x);
        sm[base + o + 1]       = f2tf(v.y);
        sm[base + (2 - o)]     = f2tf(v.z);
        sm[base + (2 - o) + 1] = f2tf(v.w);
    };

    float acc[4][8][4];
#pragma unroll
    for (int i = 0; i < 4; i++)
#pragma unroll
        for (int j = 0; j < 8; j++)
#pragma unroll
            for (int t = 0; t < 4; t++) acc[i][j][t] = 0.0f;

    // prologue: chunk 0
    {
        float4 a0 = *(const float4*)Ag0;
        float4 a1 = *(const float4*)Ag1;
        float4 b0 = *(const float4*)Bg0;
        float4 b1 = *(const float4*)Bg1;
        float4 b2 = *(const float4*)Bg2;
        float4 b3 = *(const float4*)Bg3;
        sts4(sA[0], lr, a0);       sts4(sA[0], lr + 64, a1);
        sts4(sB[0], lr, b0);       sts4(sB[0], lr + 64, b1);
        sts4(sB[0], lr + 128, b2); sts4(sB[0], lr + 192, b3);
    }
    __syncthreads();

    const int q  = lane >> 2;            // 0..7
    const int kk = lane & 3;             // 0..3
    const int cx = 2 * q;

    const int NIT = CDIM / 16;           // 32
    for (int it = 0; it < NIT; it++) {
        const int buf = it & 1;
        float4 ra0, ra1, rb0, rb1, rb2, rb3;
        if (it + 1 < NIT) {
            const int ko = (it + 1) * 16;
            ra0 = *(const float4*)(Ag0 + ko);
            ra1 = *(const float4*)(Ag1 + ko);
            rb0 = *(const float4*)(Bg0 + ko);
            rb1 = *(const float4*)(Bg1 + ko);
            rb2 = *(const float4*)(Bg2 + ko);
            rb3 = *(const float4*)(Bg3 + ko);
        }
        const uint32_t* sAb = sA[buf];
        const uint32_t* sBb = sB[buf];
#pragma unroll
        for (int ks = 0; ks < 2; ks++) {
            const int ka = ((ks << 3) + kk) ^ cx;
            const int kb = ka ^ 4;
            uint32_t af[4][4], bf[8][2];
#pragma unroll
            for (int mt = 0; mt < 4; mt++) {
                const int rb_ = (wm * 64 + mt * 16 + q) * 16;
                af[mt][0] = sAb[rb_ + ka];
                af[mt][1] = sAb[rb_ + 128 + ka];
                af[mt][2] = sAb[rb_ + kb];
                af[mt][3] = sAb[rb_ + 128 + kb];
            }
#pragma unroll
            for (int nt = 0; nt < 8; nt++) {
                const int rn = (wn * 64 + nt * 8 + q) * 16;
                bf[nt][0] = sBb[rn + ka];
                bf[nt][1] = sBb[rn + kb];
            }
#pragma unroll
            for (int mt = 0; mt < 4; mt++)
#pragma unroll
                for (int nt = 0; nt < 8; nt++)
                    mma_tf32(acc[mt][nt], af[mt], bf[nt]);
        }
        if (it + 1 < NIT) {
            const int nb = buf ^ 1;
            sts4(sA[nb], lr, ra0);       sts4(sA[nb], lr + 64, ra1);
            sts4(sB[nb], lr, rb0);       sts4(sB[nb], lr + 64, rb1);
            sts4(sB[nb], lr + 128, rb2); sts4(sB[nb], lr + 192, rb3);
            __syncthreads();
        }
    }

    // epilogue: c0/c1 -> (row q, cols 2kk,2kk+1); c2/c3 -> row q+8
#pragma unroll
    for (int mt = 0; mt < 4; mt++) {
        const int m = m0 + wm * 64 + mt * 16 + q;
        const float* rrow = resid ? (resid + (size_t)(m & (TDIM - 1)) * CDIM)
                                  : nullptr;
#pragma unroll
        for (int nt = 0; nt < 8; nt++) {
            const int n = n0 + wn * 64 + nt * 8 + 2 * kk;
            const float bx = bias[n], by = bias[n + 1];
            float2 o0 = make_float2((acc[mt][nt][0] + bx) * alpha,
                                    (acc[mt][nt][1] + by) * alpha);
            float2 o1 = make_float2((acc[mt][nt][2] + bx) * alpha,
                                    (acc[mt][nt][3] + by) * alpha);
            if (rrow) {
                o0.x += rrow[n]; o0.y += rrow[n + 1];
            }
            *(float2*)(Out + (size_t)m * outStride + n) = o0;
            if (rrow) {
                const float* rrow1 = resid + (size_t)((m + 8) & (TDIM - 1)) * CDIM;
                o1.x += rrow1[n]; o1.y += rrow1[n + 1];
            }
            *(float2*)(Out + (size_t)(m + 8) * outStride + n) = o1;
        }
    }
}

// ---------------- flash attention via mma.sync tf32 (unchanged, passing) ----
// CTA = (128-query tile, head, batch); 8 warps x 16 query rows.
// smem (dynamic 64KB): sK[64x64] | sVt[64x64] | sP[128x64] (sP doubles as Q stage)
__global__ void __launch_bounds__(256)
attn_mma(const float* __restrict__ q, const float* __restrict__ kv,
         float* __restrict__ ctx)
{
    extern __shared__ uint32_t sm[];
    uint32_t* sK  = sm;           // 64*64
    uint32_t* sVt = sm + 4096;    // 64*64 (V transposed: [dh][key])
    uint32_t* sP  = sm + 8192;    // 128*64

    const int tid  = threadIdx.x;
    const int lane = tid & 31;
    const int w    = tid >> 5;
    const int qr   = lane >> 2;      // 0..7
    const int kk   = lane & 3;       // 0..3
    const int t0   = blockIdx.x * 128;
    const int h    = blockIdx.y;
    const int b    = blockIdx.z;
    const int r0   = w * 16 + qr;

    // stage Q tile (pre-scaled by 1/8 in q-proj) into sP, swizzled tf32
    {
        const int r  = tid >> 1;
        const int cb = (tid & 1) * 32;
        const float* qrow = q + (size_t)(t0 + r) * CDIM + h * DH + cb;
#pragma unroll
        for (int j = 0; j < 8; j++) {
            float4 v = *(const float4*)(qrow + j * 4);
            const int c4 = (((cb >> 2) + j) ^ (r & 7)) << 2;
            uint32_t* d = sP + r * 64 + c4;
            d[0] = f2tf(v.x); d[1] = f2tf(v.y); d[2] = f2tf(v.z); d[3] = f2tf(v.w);
        }
    }
    __syncthreads();

    // Q fragments live in registers for the whole kernel
    uint32_t qa[8][4];
#pragma unroll
    for (int ks = 0; ks < 8; ks++) {
        qa[ks][0] = sP[PSW(r0,     kk + 8 * ks)];
        qa[ks][1] = sP[PSW(r0 + 8, kk + 8 * ks)];
        qa[ks][2] = sP[PSW(r0,     kk + 4 + 8 * ks)];
        qa[ks][3] = sP[PSW(r0 + 8, kk + 4 + 8 * ks)];
    }
    // (the in-loop syncs order these reads before any P write to sP)

    float o[8][4];
#pragma unroll
    for (int nt = 0; nt < 8; nt++)
#pragma unroll
        for (int t = 0; t < 4; t++) o[nt][t] = 0.0f;
    float m0 = -1e30f, m1 = -1e30f, l0 = 0.0f, l1 = 0.0f;

    const float* kvb = kv + (size_t)b * SEQK * (2 * CDIM) + h * DH;
    const int kr = tid >> 2;         // 0..63 key row
    const int kq = tid & 3;          // 16-col group

    float4 kreg[4], vreg[4];
    {
        const float* krow = kvb + (size_t)kr * (2 * CDIM) + kq * 16;
#pragma unroll
        for (int j = 0; j < 4; j++) {
            kreg[j] = *(const float4*)(krow + j * 4);
            vreg[j] = *(const float4*)(krow + CDIM + j * 4);
        }
    }

    for (int c = 0; c < SEQK / 64; c++) {
        if (c) __syncthreads();      // prior chunk's mma reads done
        // STS K (swizzled uint4)
#pragma unroll
        for (int j = 0; j < 4; j++) {
            const int c4 = ((kq * 4 + j) ^ (kr & 7)) << 2;
            uint32_t* d = sK + kr * 64 + c4;
            d[0] = f2tf(kreg[j].x); d[1] = f2tf(kreg[j].y);
            d[2] = f2tf(kreg[j].z); d[3] = f2tf(kreg[j].w);
        }
        // STS V transposed (rotation over kq keeps banks distinct)
        {
            const float* vf = (const float*)vreg;
#pragma unroll
            for (int i = 0; i < 16; i++) {
                const int idx = (i + kq * 2) & 15;
                const int dd = kq * 16 + idx;
                sVt[PSW(dd, kr)] = f2tf(vf[idx]);
            }
        }
        // prefetch next chunk into registers (overlaps mma section)
        if (c + 1 < SEQK / 64) {
            const float* krow = kvb + (size_t)((c + 1) * 64 + kr) * (2 * CDIM) + kq * 16;
#pragma unroll
            for (int j = 0; j < 4; j++) {
                kreg[j] = *(const float4*)(krow + j * 4);
                vreg[j] = *(const float4*)(krow + CDIM + j * 4);
            }
        }
        __syncthreads();

        // S = Q K^T : rows r0,r0+8; cols = 64 keys (8 n-tiles)
        float sc[8][4];
#pragma unroll
        for (int nt = 0; nt < 8; nt++)
#pragma unroll
            for (int t = 0; t < 4; t++) sc[nt][t] = 0.0f;
#pragma unroll
        for (int ks = 0; ks < 8; ks++) {
#pragma unroll
            for (int nt = 0; nt < 8; nt++) {
                uint32_t bf[2];
                bf[0] = sK[PSW(nt * 8 + qr, kk + 8 * ks)];
                bf[1] = sK[PSW(nt * 8 + qr, kk + 4 + 8 * ks)];
                mma_tf32(sc[nt], qa[ks], bf);
            }
        }

        // online softmax over this chunk (quad lanes share a row)
        float mx0 = -1e30f, mx1 = -1e30f;
#pragma unroll
        for (int nt = 0; nt < 8; nt++) {
            mx0 = fmaxf(mx0, fmaxf(sc[nt][0], sc[nt][1]));
            mx1 = fmaxf(mx1, fmaxf(sc[nt][2], sc[nt][3]));
        }
        mx0 = fmaxf(mx0, __shfl_xor_sync(0xffffffffu, mx0, 1));
        mx0 = fmaxf(mx0, __shfl_xor_sync(0xffffffffu, mx0, 2));
        mx1 = fmaxf(mx1, __shfl_xor_sync(0xffffffffu, mx1, 1));
        mx1 = fmaxf(mx1, __shfl_xor_sync(0xffffffffu, mx1, 2));
        const float m0n = fmaxf(m0, mx0), m1n = fmaxf(m1, mx1);
        const float al0 = __expf(m0 - m0n), al1 = __expf(m1 - m1n);
        float s0 = 0.0f, s1 = 0.0f;
#pragma unroll
        for (int nt = 0; nt < 8; nt++) {
            sc[nt][0] = __expf(sc[nt][0] - m0n);
            sc[nt][1] = __expf(sc[nt][1] - m0n);
            sc[nt][2] = __expf(sc[nt][2] - m1n);
            sc[nt][3] = __expf(sc[nt][3] - m1n);
            s0 += sc[nt][0] + sc[nt][1];
            s1 += sc[nt][2] + sc[nt][3];
        }
        s0 += __shfl_xor_sync(0xffffffffu, s0, 1);
        s0 += __shfl_xor_sync(0xffffffffu, s0, 2);
        s1 += __shfl_xor_sync(0xffffffffu, s1, 1);
        s1 += __shfl_xor_sync(0xffffffffu, s1, 2);
        l0 = l0 * al0 + s0;  l1 = l1 * al1 + s1;
        m0 = m0n;  m1 = m1n;
#pragma unroll
        for (int nt = 0; nt < 8; nt++) {
            o[nt][0] *= al0; o[nt][1] *= al0;
            o[nt][2] *= al1; o[nt][3] *= al1;
        }

        // write P (tf32, swizzled) for the PV mma
#pragma unroll
        for (int nt = 0; nt < 8; nt++) {
            const int cb = nt * 8 + 2 * kk;
            sP[PSW(r0, cb)]         = f2tf(sc[nt][0]);
            sP[PSW(r0, cb + 1)]     = f2tf(sc[nt][1]);
            sP[PSW(r0 + 8, cb)]     = f2tf(sc[nt][2]);
            sP[PSW(r0 + 8, cb + 1)] = f2tf(sc[nt][3]);
        }
        __syncthreads();

        // O += P V  (contraction over 64 keys)
#pragma unroll
        for (int ks = 0; ks < 8; ks++) {
            uint32_t af[4];
            af[0] = sP[PSW(r0,     kk + 8 * ks)];
            af[1] = sP[PSW(r0 + 8, kk + 8 * ks)];
            af[2] = sP[PSW(r0,     kk + 4 + 8 * ks)];
            af[3] = sP[PSW(r0 + 8, kk + 4 + 8 * ks)];
#pragma unroll
            for (int nt = 0; nt < 8; nt++) {
                uint32_t bf[2];
                bf[0] = sVt[PSW(nt * 8 + qr, kk + 8 * ks)];
                bf[1] = sVt[PSW(nt * 8 + qr, kk + 4 + 8 * ks)];
                mma_tf32(o[nt], af, bf);
            }
        }
    }

    // epilogue: ctx = O / l
    const float i0 = 1.0f / l0, i1 = 1.0f / l1;
    float* crow0 = ctx + (size_t)(b * TDIM + t0 + r0) * CDIM + h * DH;
    float* crow1 = crow0 + (size_t)8 * CDIM;
#pragma unroll
    for (int nt = 0; nt < 8; nt++) {
        const int cb = nt * 8 + 2 * kk;
        *(float2*)(crow0 + cb) = make_float2(o[nt][0] * i0, o[nt][1] * i0);
        *(float2*)(crow1 + cb) = make_float2(o[nt][2] * i1, o[nt][3] * i1);
    }
}

// ---------------- LayerNorm over C=512 -------------------------------------
__global__ void __launch_bounds__(256)
ln_kernel(const float* __restrict__ y, const float* __restrict__ gamma,
          const float* __restrict__ beta, float* __restrict__ out)
{
    __shared__ float2 sred[8];
    const int row = blockIdx.x;
    const int tid = threadIdx.x;
    const float* yr = y + (size_t)row * CDIM;
    float2 v = *(const float2*)(yr + tid * 2);
    float s1 = v.x + v.y;
    float s2 = v.x * v.x + v.y * v.y;
#pragma unroll
    for (int o = 16; o > 0; o >>= 1) {
        s1 += __shfl_xor_sync(0xffffffffu, s1, o);
        s2 += __shfl_xor_sync(0xffffffffu, s2, o);
    }
    if ((tid & 31) == 0) sred[tid >> 5] = make_float2(s1, s2);
    __syncthreads();
    float t1 = 0.f, t2 = 0.f;
#pragma unroll
    for (int i = 0; i < 8; i++) { t1 += sred[i].x; t2 += sred[i].y; }
    const float mean = t1 * (1.0f / CDIM);
    const float var  = t2 * (1.0f / CDIM) - mean * mean;
    const float rstd = rsqrtf(var + 1e-5f);
    const int c = tid * 2;
    float2 g = *(const float2*)(gamma + c);
    float2 be = *(const float2*)(beta + c);
    float2 o;
    o.x = (v.x - mean) * rstd * g.x + be.x;
    o.y = (v.y - mean) * rstd * g.y + be.y;
    *(float2*)(out + (size_t)row * CDIM + c) = o;
}

// ---------------- launch ----------------------------------------------------
extern "C" void kernel_launch(void* const* d_in, const int* in_sizes, int n_in,
                              void* d_out, int out_size) {
    const float* x   = (const float*)d_in[0];
    const float* qt  = (const float*)d_in[1];
    const float* ipw = (const float*)d_in[2];
    const float* ipb = (const float*)d_in[3];
    const float* opw = (const float*)d_in[4];
    const float* opb = (const float*)d_in[5];
    const float* lng = (const float*)d_in[6];
    const float* lnb = (const float*)d_in[7];
    float* out = (float*)d_out;

    float *pq, *pkv, *pctx, *py;
    cudaGetSymbolAddress((void**)&pq,  g_q);
    cudaGetSymbolAddress((void**)&pkv, g_kv);
    cudaGetSymbolAddress((void**)&pctx, g_ctx);
    cudaGetSymbolAddress((void**)&py,  g_y);

    cudaFuncSetAttribute(attn_mma, cudaFuncAttributeMaxDynamicSharedMemorySize,
                         65536);

    // 1) q projection (scale 1/sqrt(64) baked in): [256,512]
    gemm_tf32<<<dim3(2, 2), 256>>>(qt, ipw, ipb, 0.125f, nullptr,
                                   pq, TDIM, CDIM);
    // 2) kv projection: [65536,1024] = x @ [Wk;Wv]^T + [bk;bv]
    gemm_tf32<<<dim3(4, 512), 256>>>(x, ipw + CDIM * CDIM, ipb + CDIM, 1.0f,
                                     nullptr, pkv, BATCH * SEQK, 2 * CDIM);
    // 3) fused flash attention via mma.sync tf32 -> ctx
    attn_mma<<<dim3(TDIM / 128, HEADS, BATCH), 256, 65536>>>(pq, pkv, pctx);
    // 4) out projection + residual: [2048,512]
    gemm_tf32<<<dim3(2, 16), 256>>>(pctx, opw, opb, 1.0f, qt,
                                    py, BATCH * TDIM, CDIM);
    // 5) layernorm -> out
    ln_kernel<<<BATCH * TDIM, 256>>>(py, lng, lnb, out);
}